// round 17
// baseline (speedup 1.0000x reference)
#include <cuda_runtime.h>
#include <cuda_fp16.h>

#define NN 50000
#define NE 800000
#define NG 256
#define IND 128
#define HID 64
#define EMB 128

// ---------------- scratch (device globals; no allocation) -------------------
// INVARIANT: every accumulator below is zero at kernel_launch entry; each call
// re-zeroes what it dirties (module-load zero-init makes call 1 clean).
__device__ int g_batch[NN];
__device__ alignas(8) float2 g_degcnt[NN];       // {sum ew, edge count} (zeroed by scan)
__device__ unsigned long long g_scanstate[256];  // lookback words (zeroed by divclean)
__device__ int g_rowptr[NN + 1];                 // CSR row pointers
__device__ int g_cursor[NN];                     // scatter cursors

struct __align__(8) Edge { int s; float c; };
__device__ Edge g_es[NE];        // dst-sorted (src, coef) pairs

__device__ float g_dis[NN];
// h stored as half2 (col pairs 2l,2l+1): halves gather traffic; math stays fp32
__device__ alignas(16) __half2 g_h1h[(size_t)NN * 32];   // x @ W1
__device__ alignas(16) __half2 g_hrh[(size_t)NN * 32];   // relu(A*h1 + b1)
__device__ alignas(16) __half2 g_agg2h[(size_t)NN * 32]; // A * hr (half storage)
__device__ alignas(16) float g_pool[NG * EMB];           // zeroed by divclean
__device__ float g_cnt[NG];                              // zeroed by divclean

// vector f32 reductions (sm_90+)
__device__ __forceinline__ void red_add_v4(float* p, float a, float b, float c, float d) {
    asm volatile("red.global.add.v4.f32 [%0], {%1,%2,%3,%4};"
                 :: "l"(p), "f"(a), "f"(b), "f"(c), "f"(d) : "memory");
}
__device__ __forceinline__ void red_add_v2(float2* p, float a, float b) {
    asm volatile("red.global.add.v2.f32 [%0], {%1,%2};"
                 :: "l"(p), "f"(a), "f"(b) : "memory");
}

// ---------------- inline dtype probes (thread 0 + smem broadcast) -----------
__device__ __forceinline__ int probe_edge64(const void* ei) {
    const int* w = (const int*)ei;
    int e64 = 1;
#pragma unroll
    for (int k = 0; k < 8; k++)
        if (w[2 * (k * (NE / 8)) + 1] != 0) e64 = 0;
    return e64;
}
__device__ __forceinline__ int probe_batch64(const void* batch) {
    const int* w = (const int*)batch;
    int b64 = 1;
#pragma unroll
    for (int k = 0; k < 8; k++)
        if (w[2 * (10000 + k * 1500) + 1] != 0) b64 = 0;
    return b64;
}

// ---------------- edge histogram/degree + batch convert (fused) -------------
__global__ void k_cvt(const void* ei, const float* __restrict__ ew, const void* batch) {
    __shared__ int s_e64, s_b64;
    if (threadIdx.x == 0) { s_e64 = probe_edge64(ei); s_b64 = probe_batch64(batch); }
    __syncthreads();
    int e = blockIdx.x * 256 + threadIdx.x;
    if (e < NE) {
        int d = s_e64 ? (int)((const long long*)ei)[NE + e] : ((const int*)ei)[NE + e];
        red_add_v2(&g_degcnt[d], ew[e], 1.0f);   // one v2 RED: {deg+=w, cnt+=1}
    }
    if (e < NN) {
        int b = s_b64 ? (int)((const long long*)batch)[e] : ((const int*)batch)[e];
        g_batch[e] = b;
        unsigned mask = __match_any_sync(__activemask(), b);
        int leader = __ffs(mask) - 1;
        if ((threadIdx.x & 31) == leader)
            atomicAdd(&g_cnt[b], (float)__popc(mask));
    }
}

// ---------------- single-kernel scan (decoupled lookback) + finalize --------
__global__ void k_scanall() {
    __shared__ int sm[256];
    __shared__ int s_off;
    int t = threadIdx.x, b = blockIdx.x;
    int i = b * 256 + t;
    int v = (i < NN) ? (int)g_degcnt[i].y : 0;
    sm[t] = v;
    __syncthreads();
#pragma unroll
    for (int off = 1; off < 256; off <<= 1) {
        int add = (t >= off) ? sm[t - off] : 0;
        __syncthreads();
        sm[t] += add;
        __syncthreads();
    }
    int total = sm[255];

    if (t == 0) {
        unsigned long long w = ((b == 0 ? 2ULL : 1ULL) << 62) | (unsigned)total;
        atomicExch(&g_scanstate[b], w);
        if (b == 0) s_off = 0;
    }
    if (b > 0 && t < 32) {   // warp 0: parallel lookback
        int offset = 0;
        int base = b - 1;
        for (;;) {
            int idx = base - t;
            unsigned long long w = 0;
            if (idx >= 0) {
                do { w = *(volatile unsigned long long*)&g_scanstate[idx]; }
                while ((w >> 62) == 0);
            }
            unsigned inclm = __ballot_sync(0xffffffffu, idx >= 0 && (w >> 62) == 2ULL);
            int stop = inclm ? (__ffs(inclm) - 1) : 32;
            int val = (idx >= 0 && t <= stop) ? (int)(unsigned)w : 0;
#pragma unroll
            for (int o = 16; o; o >>= 1) val += __shfl_xor_sync(0xffffffffu, val, o);
            offset += val;
            if (inclm) break;
            base -= 32;
        }
        if (t == 0) {
            s_off = offset;
            atomicExch(&g_scanstate[b], (2ULL << 62) | (unsigned)(offset + total));
        }
    }
    __syncthreads();

    if (i < NN) {
        int r = s_off + sm[t] - v;   // exclusive prefix
        g_rowptr[i] = r;
        g_cursor[i] = r;
        g_dis[i] = rsqrtf(1.0f + g_degcnt[i].x);   // self-loop weight 1 analytic
        g_degcnt[i] = make_float2(0.0f, 0.0f);     // clean for next call
        if (i == NN - 1) g_rowptr[NN] = NE;
    }
}

// scatter edges into dst-sorted order with precomputed coefficient (one ST.64)
__global__ void k_scatter(const void* ei, const float* __restrict__ ew) {
    __shared__ int s_e64;
    if (threadIdx.x == 0) s_e64 = probe_edge64(ei);
    __syncthreads();
    int e = blockIdx.x * 256 + threadIdx.x;
    if (e >= NE) return;
    int s, d;
    if (s_e64) {
        const long long* p = (const long long*)ei;
        s = (int)p[e];
        d = (int)p[NE + e];
    } else {
        const int* p = (const int*)ei;
        s = p[e];
        d = p[NE + e];
    }
    int pos = atomicAdd(&g_cursor[d], 1);
    Edge out;
    out.s = s;
    out.c = g_dis[s] * ew[e] * g_dis[d];
    g_es[pos] = out;
}

// ---------------- f32x2 GEMM, quad-k LDS.128 inner loop ---------------------
// C = A @ W. u64 accumulators hold (even-k, odd-k) partial sums.
// Per 4-k step: ONE LDS.128 broadcast per node (xs) + ONE LDS.128 per output
// col (Wst) feed 2 FMA2 per (node,col) -> (MT+VEC) LDS per 2*MT*VEC FMA2.
// Wst row stride INP = IN+4 (132 = 4 mod 32): each 8-lane LDS.128 phase
// covers all 32 banks exactly once -> conflict-free.
// AHALF: A rows stored as __half. EPI=1: half2 colpairs -> g_h1h.
// EPI=2: regroup via smem, relu(+bias), v4-RED into g_pool (mean pool).
template <int IN, int OUT, int EPI, bool AHALF>
__device__ __forceinline__ void gemm_f32x2(const void* __restrict__ A,
                                           const float* __restrict__ W,
                                           const float* __restrict__ bias) {
    constexpr int MT = 8;
    constexpr int VEC = OUT / 32;
    constexpr int INP = IN + 4;       // 4 mod 32 -> conflict-free LDS.128
    constexpr int KB = 32;
    __shared__ __align__(16) float Wst[OUT * INP];
    __shared__ __align__(16) float xs[8][MT][KB];
    __shared__ __align__(16) float stg[8][OUT];

    for (int i = threadIdx.x; i < IN * OUT; i += blockDim.x) {
        int k = i / OUT, c = i % OUT;
        Wst[c * INP + k] = W[i];
    }
    __syncthreads();

    const int warp = threadIdx.x >> 5;
    const int lane = threadIdx.x & 31;
    const int n0 = (blockIdx.x * 8 + warp) * MT;
    if (n0 >= NN) return;

    unsigned long long acc[MT][VEC];
#pragma unroll
    for (int m = 0; m < MT; m++)
#pragma unroll
        for (int c = 0; c < VEC; c++) acc[m][c] = 0ULL;

    for (int kb = 0; kb < IN; kb += KB) {
#pragma unroll
        for (int m = 0; m < MT; m++) {
            float v = 0.0f;
            if (n0 + m < NN) {
                if (AHALF)
                    v = __half2float(((const __half*)A)[(size_t)(n0 + m) * IN + kb + lane]);
                else
                    v = ((const float*)A)[(size_t)(n0 + m) * IN + kb + lane];
            }
            xs[warp][m][lane] = v;
        }
        __syncwarp();
#pragma unroll
        for (int t = 0; t < KB / 4; t++) {
            ulonglong2 xp[MT];
#pragma unroll
            for (int m = 0; m < MT; m++)
                xp[m] = *(const ulonglong2*)&xs[warp][m][4 * t];   // LDS.128 bcast
            ulonglong2 wp[VEC];
#pragma unroll
            for (int c = 0; c < VEC; c++)
                wp[c] = *(const ulonglong2*)&Wst[(lane + 32 * c) * INP + kb + 4 * t];
#pragma unroll
            for (int m = 0; m < MT; m++)
#pragma unroll
                for (int c = 0; c < VEC; c++) {
                    asm("fma.rn.f32x2 %0, %1, %2, %0;"
                        : "+l"(acc[m][c]) : "l"(xp[m].x), "l"(wp[c].x));
                    asm("fma.rn.f32x2 %0, %1, %2, %0;"
                        : "+l"(acc[m][c]) : "l"(xp[m].y), "l"(wp[c].y));
                }
        }
        __syncwarp();
    }

#pragma unroll
    for (int m = 0; m < MT; m++) {
        int n = n0 + m;
        if (n >= NN) break;  // uniform across warp
        float val[VEC];
#pragma unroll
        for (int c = 0; c < VEC; c++) {
            float lo = __uint_as_float((unsigned)acc[m][c]);
            float hi = __uint_as_float((unsigned)(acc[m][c] >> 32));
            val[c] = lo + hi;
        }
#pragma unroll
        for (int c = 0; c < VEC; c++) stg[warp][lane + 32 * c] = val[c];
        __syncwarp();
        if (EPI == 1) {
            float2 v = *(const float2*)&stg[warp][2 * lane];  // cols 2l, 2l+1
            g_h1h[(size_t)n * 32 + lane] = __float22half2_rn(v);
        } else {
            float4 v = *(const float4*)&stg[warp][4 * lane];
            float4 b = ((const float4*)bias)[lane];
            v.x = fmaxf(v.x + b.x, 0.0f);
            v.y = fmaxf(v.y + b.y, 0.0f);
            v.z = fmaxf(v.z + b.z, 0.0f);
            v.w = fmaxf(v.w + b.w, 0.0f);
            int g = g_batch[n];
            red_add_v4(g_pool + g * EMB + 4 * lane, v.x, v.y, v.z, v.w);
        }
        __syncwarp();
    }
}

__global__ void __launch_bounds__(256) k_gemm1(const float* __restrict__ x,
                                               const float* __restrict__ W1) {
    gemm_f32x2<IND, HID, 1, false>(x, W1, nullptr);
}
__global__ void __launch_bounds__(256) k_gemm2pool(const float* __restrict__ W2,
                                                   const float* __restrict__ b2) {
    gemm_f32x2<HID, EMB, 2, true>(g_agg2h, W2, b2);
}

// ---------------- CSR aggregation, warp per dst node, half2 gathers ---------
template <bool BIASRELU>
__device__ __forceinline__ void agg_body(const __half2* __restrict__ H,
                                         const float* __restrict__ bias,
                                         __half2* __restrict__ O) {
    int node = (blockIdx.x * blockDim.x + threadIdx.x) >> 5;
    int lane = threadIdx.x & 31;
    if (node >= NN) return;

    int start = g_rowptr[node];
    int end = g_rowptr[node + 1];

    float s = g_dis[node];
    s *= s;
    float2 h = __half22float2(H[(size_t)node * 32 + lane]);
    float2 acc = {s * h.x, s * h.y};

    int k = start;
    int n4 = start + ((end - start) & ~3);
    for (; k < n4; k += 4) {
        Edge e0 = g_es[k], e1 = g_es[k + 1], e2 = g_es[k + 2], e3 = g_es[k + 3];
        float2 h0 = __half22float2(H[(size_t)e0.s * 32 + lane]);
        float2 h1 = __half22float2(H[(size_t)e1.s * 32 + lane]);
        float2 h2 = __half22float2(H[(size_t)e2.s * 32 + lane]);
        float2 h3 = __half22float2(H[(size_t)e3.s * 32 + lane]);
        acc.x = fmaf(e0.c, h0.x, acc.x); acc.y = fmaf(e0.c, h0.y, acc.y);
        acc.x = fmaf(e1.c, h1.x, acc.x); acc.y = fmaf(e1.c, h1.y, acc.y);
        acc.x = fmaf(e2.c, h2.x, acc.x); acc.y = fmaf(e2.c, h2.y, acc.y);
        acc.x = fmaf(e3.c, h3.x, acc.x); acc.y = fmaf(e3.c, h3.y, acc.y);
    }
    for (; k < end; k++) {
        Edge e = g_es[k];
        float2 hh = __half22float2(H[(size_t)e.s * 32 + lane]);
        acc.x = fmaf(e.c, hh.x, acc.x);
        acc.y = fmaf(e.c, hh.y, acc.y);
    }

    if (BIASRELU) {
        float2 b = ((const float2*)bias)[lane];
        acc.x = fmaxf(acc.x + b.x, 0.0f);
        acc.y = fmaxf(acc.y + b.y, 0.0f);
    }
    O[(size_t)node * 32 + lane] = __float22half2_rn(acc);
}

__global__ void k_agg1(const float* __restrict__ b1) {
    agg_body<true>(g_h1h, b1, g_hrh);
}
__global__ void k_agg2() {
    agg_body<false>(g_hrh, nullptr, g_agg2h);
}

// ---------------- mean divide + state cleanup for next call -----------------
__global__ void k_divclean(float* __restrict__ out) {
    int gid = blockIdx.x * 256 + threadIdx.x;
    float c = fmaxf(g_cnt[gid >> 7], 1.0f);
    out[gid] = g_pool[gid] / c;
    g_pool[gid] = 0.0f;
    __syncthreads();
    if (threadIdx.x < 2) g_cnt[blockIdx.x * 2 + threadIdx.x] = 0.0f;
    if (blockIdx.x == 0) g_scanstate[threadIdx.x] = 0ULL;
}

// ---------------- launch ----------------
extern "C" void kernel_launch(void* const* d_in, const int* in_sizes, int n_in,
                              void* d_out, int out_size) {
    const float* x     = (const float*)d_in[0];
    const void*  ei    = d_in[1];  // [2, NE] int32 or int64 — probed on device
    const float* ew    = (const float*)d_in[2];
    const void*  batch = d_in[3];
    const float* W1    = (const float*)d_in[4];
    const float* b1    = (const float*)d_in[5];
    const float* W2    = (const float*)d_in[6];
    const float* b2    = (const float*)d_in[7];
    float*       out   = (float*)d_out;

    const int T = 256;
    const int NBLK = (NN + 255) / 256;    // 196
    const int GBLK = (NN + 63) / 64;      // 782 (8 nodes/warp * 8 warps)

    // CSR build (3 kernels)
    k_cvt<<<(NE + T - 1) / T, T>>>(ei, ew, batch);
    k_scanall<<<NBLK, 256>>>();
    k_scatter<<<(NE + T - 1) / T, T>>>(ei, ew);

    // layer 1: h1 = half(x@W1) ; hr = half(relu(A*h1 + b1))
    k_gemm1<<<GBLK, T>>>(x, W1);
    k_agg1<<<(NN * 32 + T - 1) / T, T>>>(b1);

    // layer 2: agg2 = half(A*hr) ; pool += relu(agg2@W2 + b2)
    k_agg2<<<(NN * 32 + T - 1) / T, T>>>();
    k_gemm2pool<<<GBLK, T>>>(W2, b2);

    // mean + cleanup (leaves all accumulators zero for next call)
    k_divclean<<<(NG * EMB) / T, T>>>(out);
}